// round 4
// baseline (speedup 1.0000x reference)
#include <cuda_runtime.h>
#include <cstdint>

// YoloLayer: x (B, 3*12, G, G) f32 -> out (B, 3*G*G, 12) f32
// 2 spatial points per thread (float2 loads), 2D grid (y = b*3+a),
// smem staging so global stores are perfectly coalesced float4 streams.

#define G_  152
#define GG_ (G_ * G_)        // 23104
#define NA_ 3
#define NATTR 12
#define EXP_CLAMP_ 1000.0f
#define BLK 256
#define PTS (BLK * 2)        // 512 spatial points per block

__device__ __forceinline__ float sigmoidf_(float v) {
    return __fdividef(1.0f, 1.0f + __expf(-v));
}

__global__ __launch_bounds__(BLK)
void yolo_kernel(const float* __restrict__ x,
                 const float* __restrict__ anchors,
                 const int*   __restrict__ img_size_p,
                 float* __restrict__ out)
{
    __shared__ float sbuf[PTS * NATTR];   // 24 KB, mirrors output layout for this block

    const int ba = blockIdx.y;                 // b*3 + a
    const int s0 = blockIdx.x * PTS;           // first spatial point of this block
    const int tid = threadIdx.x;
    const int s  = s0 + tid * 2;               // even; s,s+1 share a row (G even)

    // img_size may arrive as int32 or float32 bits.
    int ibits = img_size_p[0];
    float img = (ibits >= 1 && ibits <= (1 << 20)) ? (float)ibits : __int_as_float(ibits);
    const float stride = img / (float)G_;

    const int valid = min(PTS, GG_ - s0);      // points this block actually covers

    if (s < GG_) {
        int a  = ba - (ba / NA_) * NA_;        // ba % 3
        int gy = s / G_;                       // constant-div -> mul/shift
        int gx = s - gy * G_;

        const float an0 = anchors[a * 5 + 0];
        const float an1 = anchors[a * 5 + 1];
        const float an2 = anchors[a * 5 + 2];

        // 12 channel-strided float2 loads (8B aligned: GG_ even, s even)
        const float* base = x + (size_t)ba * NATTR * GG_ + s;
        float2 p[NATTR];
#pragma unroll
        for (int attr = 0; attr < NATTR; ++attr)
            p[attr] = __ldcs(reinterpret_cast<const float2*>(base + (size_t)attr * GG_));

        float4* sv = reinterpret_cast<float4*>(sbuf + tid * 2 * NATTR);

        // point 0 (gx) and point 1 (gx+1)
        {
            float c0 = (sigmoidf_(p[0].x) + (float)gx) * stride;
            float c1 = (sigmoidf_(p[1].x) + (float)gy) * stride;
            float c2 =  sigmoidf_(p[2].x);
            float c3 = fminf(__expf(p[3].x), EXP_CLAMP_) * an0;
            float c4 = fminf(__expf(p[4].x), EXP_CLAMP_) * an1;
            float c5 = fminf(__expf(p[5].x), EXP_CLAMP_) * an2;
            sv[0] = make_float4(c0, c1, c2, c3);
            sv[1] = make_float4(c4, c5, p[6].x, p[7].x);
            sv[2] = make_float4(sigmoidf_(p[8].x),  sigmoidf_(p[9].x),
                                sigmoidf_(p[10].x), sigmoidf_(p[11].x));
        }
        {
            float c0 = (sigmoidf_(p[0].y) + (float)(gx + 1)) * stride;
            float c1 = (sigmoidf_(p[1].y) + (float)gy) * stride;
            float c2 =  sigmoidf_(p[2].y);
            float c3 = fminf(__expf(p[3].y), EXP_CLAMP_) * an0;
            float c4 = fminf(__expf(p[4].y), EXP_CLAMP_) * an1;
            float c5 = fminf(__expf(p[5].y), EXP_CLAMP_) * an2;
            sv[3] = make_float4(c0, c1, c2, c3);
            sv[4] = make_float4(c4, c5, p[6].y, p[7].y);
            sv[5] = make_float4(sigmoidf_(p[8].y),  sigmoidf_(p[9].y),
                                sigmoidf_(p[10].y), sigmoidf_(p[11].y));
        }
    }
    __syncthreads();

    // Stream the block's results out coalesced: up to 6 chunks of 256 float4s.
    const int nf4 = valid * 3;                          // float4s to store
    float4* obase = reinterpret_cast<float4*>(out) + ((size_t)ba * GG_ + s0) * 3;
    const float4* sv4 = reinterpret_cast<const float4*>(sbuf);
#pragma unroll
    for (int k = 0; k < 6; ++k) {
        int idx = k * BLK + tid;
        if (idx < nf4)
            __stcs(obase + idx, sv4[idx]);
    }
}

extern "C" void kernel_launch(void* const* d_in, const int* in_sizes, int n_in,
                              void* d_out, int out_size)
{
    const float* x        = (const float*)d_in[0];
    const float* anchors  = (const float*)d_in[1];
    const int*   img_size = (const int*)d_in[2];
    float* out = (float*)d_out;

    int B = in_sizes[0] / (NA_ * NATTR * GG_);

    dim3 grid((GG_ + PTS - 1) / PTS, B * NA_);   // (46, B*3)
    yolo_kernel<<<grid, BLK>>>(x, anchors, img_size, out);
}

// round 5
// speedup vs baseline: 1.0111x; 1.0111x over previous
#include <cuda_runtime.h>
#include <cstdint>

// YoloLayer: x (B, 3*12, G, G) f32 -> out (B, 3*G*G, 12) f32
// 1 point/thread; warp-private smem staging (no block barrier) so global
// stores are perfectly coalesced float4 streams. Grid (91, 3, B).

#define G_  152
#define GG_ (G_ * G_)        // 23104 (= 90*256 + 64; divisible by 32)
#define NA_ 3
#define NATTR 12
#define EXP_CLAMP_ 1000.0f
#define BLK 256

__device__ __forceinline__ float sigmoidf_(float v) {
    return __fdividef(1.0f, 1.0f + __expf(-v));
}

__global__ __launch_bounds__(BLK)
void yolo_kernel(const float* __restrict__ x,
                 const float* __restrict__ anchors,
                 const int*   __restrict__ img_size_p,
                 float* __restrict__ out)
{
    __shared__ float sbuf[BLK * NATTR];          // 12 KB; 1536 B per warp

    const int tid  = threadIdx.x;
    const int lane = tid & 31;
    const int a    = blockIdx.y;                 // anchor index directly
    const int ba   = blockIdx.z * NA_ + a;       // b*3 + a
    const int s    = blockIdx.x * BLK + tid;     // spatial point
    const int warpStart = blockIdx.x * BLK + (tid & ~31);

    if (warpStart >= GG_) return;                // whole warp out (GG_ % 32 == 0)

    // img_size may arrive as int32 or float32 bits.
    int ibits = img_size_p[0];
    float img = (ibits >= 1 && ibits <= (1 << 20)) ? (float)ibits : __int_as_float(ibits);
    const float stride = img / (float)G_;

    int gy = s / G_;                             // constant div -> mul/shift
    int gx = s - gy * G_;

    const float an0 = anchors[a * 5 + 0];
    const float an1 = anchors[a * 5 + 1];
    const float an2 = anchors[a * 5 + 2];

    // 12 channel-strided scalar loads; lanes consecutive in s -> full 128B lines.
    const float* base = x + (size_t)ba * NATTR * GG_ + s;
    float p[NATTR];
#pragma unroll
    for (int attr = 0; attr < NATTR; ++attr)
        p[attr] = __ldcs(base + attr * GG_);

    float c0 = (sigmoidf_(p[0]) + (float)gx) * stride;
    float c1 = (sigmoidf_(p[1]) + (float)gy) * stride;
    float c2 =  sigmoidf_(p[2]);
    float c3 = fminf(__expf(p[3]), EXP_CLAMP_) * an0;   // (anchor/stride)*stride cancels
    float c4 = fminf(__expf(p[4]), EXP_CLAMP_) * an1;
    float c5 = fminf(__expf(p[5]), EXP_CLAMP_) * an2;

    // Stage this warp's 32 points (1536 B) in its own smem slice.
    float4* sv = reinterpret_cast<float4*>(sbuf + tid * NATTR);
    sv[0] = make_float4(c0, c1, c2, c3);
    sv[1] = make_float4(c4, c5, p[6], p[7]);
    sv[2] = make_float4(sigmoidf_(p[8]),  sigmoidf_(p[9]),
                        sigmoidf_(p[10]), sigmoidf_(p[11]));
    __syncwarp();

    // Warp streams its 1536 B out as 3 coalesced float4 wavefront sets.
    const float4* wbuf = reinterpret_cast<const float4*>(sbuf + (tid & ~31) * NATTR);
    float4* obase = reinterpret_cast<float4*>(out) + ((size_t)ba * GG_ + warpStart) * 3;
    __stcs(obase + lane,      wbuf[lane]);
    __stcs(obase + lane + 32, wbuf[lane + 32]);
    __stcs(obase + lane + 64, wbuf[lane + 64]);
}

extern "C" void kernel_launch(void* const* d_in, const int* in_sizes, int n_in,
                              void* d_out, int out_size)
{
    const float* x        = (const float*)d_in[0];
    const float* anchors  = (const float*)d_in[1];
    const int*   img_size = (const int*)d_in[2];
    float* out = (float*)d_out;

    int B = in_sizes[0] / (NA_ * NATTR * GG_);

    dim3 grid((GG_ + BLK - 1) / BLK, NA_, B);    // (91, 3, B)
    yolo_kernel<<<grid, BLK>>>(x, anchors, img_size, out);
}

// round 6
// speedup vs baseline: 1.0120x; 1.0009x over previous
#include <cuda_runtime.h>
#include <cstdint>

// YoloLayer: x (B, 3*12, G, G) f32 -> out (B, 3*G*G, 12) f32
// 1 point/thread; warp-private smem staging (no block barrier) so global
// stores are coalesced float4 streams. Grid (91, 3, B).
// Input: __ldcs (evict-first, read-once). Output: default write-back stores
// so dirty lines live in L2 across graph replays instead of streaming to HBM.

#define G_  152
#define GG_ (G_ * G_)        // 23104 (divisible by 32)
#define NA_ 3
#define NATTR 12
#define EXP_CLAMP_ 1000.0f
#define BLK 256

__device__ __forceinline__ float sigmoidf_(float v) {
    return __fdividef(1.0f, 1.0f + __expf(-v));
}

__global__ __launch_bounds__(BLK)
void yolo_kernel(const float* __restrict__ x,
                 const float* __restrict__ anchors,
                 const int*   __restrict__ img_size_p,
                 float* __restrict__ out)
{
    __shared__ float sbuf[BLK * NATTR];          // 12 KB; 1536 B per warp

    const int tid  = threadIdx.x;
    const int lane = tid & 31;
    const int a    = blockIdx.y;                 // anchor index directly
    const int ba   = blockIdx.z * NA_ + a;       // b*3 + a
    const int s    = blockIdx.x * BLK + tid;     // spatial point
    const int warpStart = blockIdx.x * BLK + (tid & ~31);

    if (warpStart >= GG_) return;                // whole warp out (GG_ % 32 == 0)

    // img_size may arrive as int32 or float32 bits.
    int ibits = img_size_p[0];
    float img = (ibits >= 1 && ibits <= (1 << 20)) ? (float)ibits : __int_as_float(ibits);
    const float stride = img / (float)G_;

    int gy = s / G_;                             // constant div -> mul/shift
    int gx = s - gy * G_;

    const float an0 = anchors[a * 5 + 0];
    const float an1 = anchors[a * 5 + 1];
    const float an2 = anchors[a * 5 + 2];

    // 12 channel-strided scalar loads; lanes consecutive in s -> full 128B lines.
    // Evict-first: input is dead after this read, don't hold L2 capacity.
    const float* base = x + (size_t)ba * NATTR * GG_ + s;
    float p[NATTR];
#pragma unroll
    for (int attr = 0; attr < NATTR; ++attr)
        p[attr] = __ldcs(base + attr * GG_);

    float c0 = (sigmoidf_(p[0]) + (float)gx) * stride;
    float c1 = (sigmoidf_(p[1]) + (float)gy) * stride;
    float c2 =  sigmoidf_(p[2]);
    float c3 = fminf(__expf(p[3]), EXP_CLAMP_) * an0;   // (anchor/stride)*stride cancels
    float c4 = fminf(__expf(p[4]), EXP_CLAMP_) * an1;
    float c5 = fminf(__expf(p[5]), EXP_CLAMP_) * an2;

    // Stage this warp's 32 points (1536 B) in its own smem slice.
    float4* sv = reinterpret_cast<float4*>(sbuf + tid * NATTR);
    sv[0] = make_float4(c0, c1, c2, c3);
    sv[1] = make_float4(c4, c5, p[6], p[7]);
    sv[2] = make_float4(sigmoidf_(p[8]),  sigmoidf_(p[9]),
                        sigmoidf_(p[10]), sigmoidf_(p[11]));
    __syncwarp();

    // Warp streams its 1536 B out as 3 coalesced float4 wavefront sets.
    // Default write-back stores: let output live in L2 across replays.
    const float4* wbuf = reinterpret_cast<const float4*>(sbuf + (tid & ~31) * NATTR);
    float4* obase = reinterpret_cast<float4*>(out) + ((size_t)ba * GG_ + warpStart) * 3;
    obase[lane]      = wbuf[lane];
    obase[lane + 32] = wbuf[lane + 32];
    obase[lane + 64] = wbuf[lane + 64];
}

extern "C" void kernel_launch(void* const* d_in, const int* in_sizes, int n_in,
                              void* d_out, int out_size)
{
    const float* x        = (const float*)d_in[0];
    const float* anchors  = (const float*)d_in[1];
    const int*   img_size = (const int*)d_in[2];
    float* out = (float*)d_out;

    int B = in_sizes[0] / (NA_ * NATTR * GG_);

    dim3 grid((GG_ + BLK - 1) / BLK, NA_, B);    // (91, 3, B)
    yolo_kernel<<<grid, BLK>>>(x, anchors, img_size, out);
}